// round 4
// baseline (speedup 1.0000x reference)
#include <cuda_runtime.h>
#include <cuda_bf16.h>
#include <math.h>

#define MAXV    2000000
#define NMESH   4

// Scratch: Lx (3 comps) + row_sum packed as float4 per row. 32 MB.
__device__ float4 d_acc[MAXV];
// Padded gather table: (x, y, z, 0) so gathers are a single LDG.128.
__device__ float4 d_verts4[MAXV];
__device__ float  d_inv_nvpm[NMESH];

// ---------------------------------------------------------------------------
// Kernel 1: build padded verts table, zero accumulator, zero output scalar.
// 4 vertices per thread: 3 coalesced float4 reads -> 4 float4 writes + zeros.
// ---------------------------------------------------------------------------
__global__ void prep_kernel(const float4* __restrict__ verts4in,  // verts as float4[3V/4]
                            float* __restrict__ out, int v) {
    const float4 z = make_float4(0.f, 0.f, 0.f, 0.f);
    int t = blockIdx.x * blockDim.x + threadIdx.x;
    int base = t * 4;                       // first vertex handled by this thread
    if (base + 3 < v) {
        // 4 vertices = 12 floats = 3 float4 loads at float4-index 3*t
        float4 a = __ldg(&verts4in[3 * t + 0]);   // v0.x v0.y v0.z v1.x
        float4 b = __ldg(&verts4in[3 * t + 1]);   // v1.y v1.z v2.x v2.y
        float4 c = __ldg(&verts4in[3 * t + 2]);   // v2.z v3.x v3.y v3.z
        d_verts4[base + 0] = make_float4(a.x, a.y, a.z, 0.f);
        d_verts4[base + 1] = make_float4(a.w, b.x, b.y, 0.f);
        d_verts4[base + 2] = make_float4(b.z, b.w, c.x, 0.f);
        d_verts4[base + 3] = make_float4(c.y, c.z, c.w, 0.f);
        d_acc[base + 0] = z;
        d_acc[base + 1] = z;
        d_acc[base + 2] = z;
        d_acc[base + 3] = z;
    } else {
        const float* verts = (const float*)verts4in;
        for (int i = base; i < v; i++) {
            d_verts4[i] = make_float4(verts[3 * i], verts[3 * i + 1],
                                      verts[3 * i + 2], 0.f);
            d_acc[i] = z;
        }
    }
    if (blockIdx.x == 0 && threadIdx.x == 0)
        out[0] = 0.f;
}

// ---------------------------------------------------------------------------
// Kernel 2: mesh vertex counts via binary search (verts_mesh_idx is sorted)
// ---------------------------------------------------------------------------
__global__ void mesh_count_kernel(const int* __restrict__ idx, int v) {
    int m = threadIdx.x;
    if (m >= NMESH) return;
    auto lb = [&](int val) {
        int lo = 0, hi = v;
        while (lo < hi) {
            int mid = (lo + hi) >> 1;
            if (__ldg(idx + mid) < val) lo = mid + 1; else hi = mid;
        }
        return lo;
    };
    int s = lb(m);
    int e = lb(m + 1);
    int cnt = e - s;
    d_inv_nvpm[m] = (cnt > 0) ? (1.f / (float)cnt) : 0.f;
}

// ---------------------------------------------------------------------------
// Kernel 3: COO scatter.  One thread handles 8 nnz.  Streams use evict-first
// (__ldcs); gathers are single LDG.128 from L2-resident verts4; each nnz
// contributes one red.global.add.v4.f32.  All 8 gathers issued before REDs.
// ---------------------------------------------------------------------------
__device__ __forceinline__ void red_add_v4(float4* addr, float x, float y,
                                           float z, float w) {
    asm volatile("red.global.add.v4.f32 [%0], {%1, %2, %3, %4};"
                 :: "l"(addr), "f"(x), "f"(y), "f"(z), "f"(w)
                 : "memory");
}

__device__ __forceinline__ void scatter_one(float v, int r, int c) {
    float4 p = __ldg(&d_verts4[c]);
    red_add_v4(&d_acc[r], v * p.x, v * p.y, v * p.z, v);
}

__global__ void scatter_kernel(const float* __restrict__ vals,
                               const int*   __restrict__ rows,
                               const int*   __restrict__ cols,
                               int nnz) {
    int t = blockIdx.x * blockDim.x + threadIdx.x;
    long long base = (long long)t * 8;
    if (base + 7 < nnz) {
        float4 v0 = __ldcs(reinterpret_cast<const float4*>(vals + base));
        float4 v1 = __ldcs(reinterpret_cast<const float4*>(vals + base + 4));
        int4   r0 = __ldcs(reinterpret_cast<const int4*>(rows + base));
        int4   r1 = __ldcs(reinterpret_cast<const int4*>(rows + base + 4));
        int4   c0 = __ldcs(reinterpret_cast<const int4*>(cols + base));
        int4   c1 = __ldcs(reinterpret_cast<const int4*>(cols + base + 4));
        // Issue all 8 gathers first (MLP for L2 latency).
        float4 p0 = __ldg(&d_verts4[c0.x]);
        float4 p1 = __ldg(&d_verts4[c0.y]);
        float4 p2 = __ldg(&d_verts4[c0.z]);
        float4 p3 = __ldg(&d_verts4[c0.w]);
        float4 p4 = __ldg(&d_verts4[c1.x]);
        float4 p5 = __ldg(&d_verts4[c1.y]);
        float4 p6 = __ldg(&d_verts4[c1.z]);
        float4 p7 = __ldg(&d_verts4[c1.w]);
        red_add_v4(&d_acc[r0.x], v0.x * p0.x, v0.x * p0.y, v0.x * p0.z, v0.x);
        red_add_v4(&d_acc[r0.y], v0.y * p1.x, v0.y * p1.y, v0.y * p1.z, v0.y);
        red_add_v4(&d_acc[r0.z], v0.z * p2.x, v0.z * p2.y, v0.z * p2.z, v0.z);
        red_add_v4(&d_acc[r0.w], v0.w * p3.x, v0.w * p3.y, v0.w * p3.z, v0.w);
        red_add_v4(&d_acc[r1.x], v1.x * p4.x, v1.x * p4.y, v1.x * p4.z, v1.x);
        red_add_v4(&d_acc[r1.y], v1.y * p5.x, v1.y * p5.y, v1.y * p5.z, v1.y);
        red_add_v4(&d_acc[r1.z], v1.z * p6.x, v1.z * p6.y, v1.z * p6.z, v1.z);
        red_add_v4(&d_acc[r1.w], v1.w * p7.x, v1.w * p7.y, v1.w * p7.z, v1.w);
    } else {
        for (long long i = base; i < nnz; i++)
            scatter_one(__ldg(vals + i), __ldg(rows + i), __ldg(cols + i));
    }
}

// ---------------------------------------------------------------------------
// Kernel 4: per-vertex loss + global reduction (READ-ONLY on d_acc).
// 2 vertices per thread for MLP.
// ---------------------------------------------------------------------------
__global__ void finalize_kernel(const int*   __restrict__ mesh_idx,
                                const float* __restrict__ coefs,
                                float* __restrict__ out,
                                int v) {
    int t = blockIdx.x * blockDim.x + threadIdx.x;
    int i0 = t * 2;
    float acc = 0.f;
    if (i0 + 1 < v) {
        float4 L0 = __ldg(&d_acc[i0]);
        float4 L1 = __ldg(&d_acc[i0 + 1]);
        float4 q0 = __ldg(&d_verts4[i0]);
        float4 q1 = __ldg(&d_verts4[i0 + 1]);
        int2   mi = __ldg(reinterpret_cast<const int2*>(mesh_idx + i0));
        float2 cf = __ldg(reinterpret_cast<const float2*>(coefs + i0));

        float nw0 = (L0.w > 0.f) ? (1.f / L0.w) : L0.w;
        float nw1 = (L1.w > 0.f) ? (1.f / L1.w) : L1.w;
        float rx0 = L0.x * nw0 - q0.x, ry0 = L0.y * nw0 - q0.y, rz0 = L0.z * nw0 - q0.z;
        float rx1 = L1.x * nw1 - q1.x, ry1 = L1.y * nw1 - q1.y, rz1 = L1.z * nw1 - q1.z;
        float l0 = sqrtf(rx0 * rx0 + ry0 * ry0 + rz0 * rz0);
        float l1 = sqrtf(rx1 * rx1 + ry1 * ry1 + rz1 * rz1);
        acc = (l0 * d_inv_nvpm[mi.x] * cf.x + l1 * d_inv_nvpm[mi.y] * cf.y)
              * (1.f / (float)NMESH);
    } else {
        for (int i = i0; i < v; i++) {
            float4 L = __ldg(&d_acc[i]);
            float nw = (L.w > 0.f) ? (1.f / L.w) : L.w;
            float4 q = __ldg(&d_verts4[i]);
            float rx = L.x * nw - q.x, ry = L.y * nw - q.y, rz = L.z * nw - q.z;
            float loss = sqrtf(rx * rx + ry * ry + rz * rz);
            acc += loss * d_inv_nvpm[__ldg(mesh_idx + i)] * __ldg(coefs + i)
                   * (1.f / (float)NMESH);
        }
    }

    // warp reduce
    #pragma unroll
    for (int off = 16; off > 0; off >>= 1)
        acc += __shfl_down_sync(0xFFFFFFFFu, acc, off);

    __shared__ float sdata[32];
    int lane = threadIdx.x & 31;
    int wid  = threadIdx.x >> 5;
    if (lane == 0) sdata[wid] = acc;
    __syncthreads();

    int nwarps = blockDim.x >> 5;
    if (wid == 0) {
        acc = (lane < nwarps) ? sdata[lane] : 0.f;
        #pragma unroll
        for (int off = 16; off > 0; off >>= 1)
            acc += __shfl_down_sync(0xFFFFFFFFu, acc, off);
        if (lane == 0)
            atomicAdd(out, acc);
    }
}

// ---------------------------------------------------------------------------
// Launch
// ---------------------------------------------------------------------------
extern "C" void kernel_launch(void* const* d_in, const int* in_sizes, int n_in,
                              void* d_out, int out_size) {
    const float* verts    = (const float*)d_in[0];
    const float* lap_vals = (const float*)d_in[1];
    const int*   lap_rows = (const int*)  d_in[2];
    const int*   lap_cols = (const int*)  d_in[3];
    const int*   mesh_idx = (const int*)  d_in[4];
    const float* coefs    = (const float*)d_in[5];
    float*       out      = (float*)d_out;

    int nnz = in_sizes[1];
    int v   = in_sizes[4];

    // 1. build padded verts table + zero accumulator + zero output
    {
        int threads = 256;
        int quads = (v + 3) / 4;
        int blocks = (quads + threads - 1) / threads;
        prep_kernel<<<blocks, threads>>>((const float4*)verts, out, v);
    }

    // 2. mesh counts (tiny)
    mesh_count_kernel<<<1, 32>>>(mesh_idx, v);

    // 3. scatter (8 nnz / thread)
    {
        int threads = 256;
        int octs = (nnz + 7) / 8;
        int blocks = (octs + threads - 1) / threads;
        scatter_kernel<<<blocks, threads>>>(lap_vals, lap_rows, lap_cols, nnz);
    }

    // 4. finalize + reduce (2 verts / thread)
    {
        int threads = 256;
        int pairs = (v + 1) / 2;
        int blocks = (pairs + threads - 1) / threads;
        finalize_kernel<<<blocks, threads>>>(mesh_idx, coefs, out, v);
    }
}